// round 13
// baseline (speedup 1.0000x reference)
#include <cuda_runtime.h>
#include <cuda_fp16.h>
#include <math.h>
#include <cstdint>

#define BATCH 4
#define SEQ   2048
#define DIM   1024
#define NHEAD 16
#define DH    64
#define MROWS (BATCH*SEQ)   // 8192

// ---------------- scratch (device globals: no allocation allowed) ----------
__device__ __half g_Xh[(size_t)MROWS*DIM];
__device__ __half g_Wh[(size_t)4*DIM*DIM];
__device__ __half g_Qh[(size_t)MROWS*DIM];
__device__ __half g_Kh[(size_t)MROWS*DIM];
__device__ __half g_Vth[(size_t)MROWS*DIM];  // [b][h][dim][seq]
__device__ __half g_Oh[(size_t)MROWS*DIM];
__device__ float2 g_RT[(size_t)SEQ*32];      // rope table: cos,sin per (s, i)

// ========================= helpers ========================================
__device__ __forceinline__ uint32_t smem_u32(const void* p) {
    uint32_t a;
    asm("{ .reg .u64 t; cvta.to.shared.u64 t, %1; cvt.u32.u64 %0, t; }"
        : "=r"(a) : "l"(p));
    return a;
}

__device__ __forceinline__ void cp_async16(uint32_t dst, const void* src) {
    asm volatile("cp.async.cg.shared.global [%0], [%1], 16;"
                 :: "r"(dst), "l"(src) : "memory");
}
#define CP_COMMIT() asm volatile("cp.async.commit_group;" ::: "memory")
#define CP_WAIT(n)  asm volatile("cp.async.wait_group %0;" :: "n"(n) : "memory")

__device__ __forceinline__ void ldsm_x4(uint32_t& r0, uint32_t& r1,
                                        uint32_t& r2, uint32_t& r3, uint32_t a) {
    asm volatile("ldmatrix.sync.aligned.m8n8.x4.shared.b16 {%0,%1,%2,%3}, [%4];"
                 : "=r"(r0), "=r"(r1), "=r"(r2), "=r"(r3) : "r"(a));
}

__device__ __forceinline__ void mma_fp16(float* d, const uint32_t* a,
                                         const uint32_t* b) {
    asm volatile("mma.sync.aligned.m16n8k16.row.col.f32.f16.f16.f32 "
                 "{%0,%1,%2,%3}, {%4,%5,%6,%7}, {%8,%9}, {%0,%1,%2,%3};"
                 : "+f"(d[0]), "+f"(d[1]), "+f"(d[2]), "+f"(d[3])
                 : "r"(a[0]), "r"(a[1]), "r"(a[2]), "r"(a[3]),
                   "r"(b[0]), "r"(b[1]));
}

__device__ __forceinline__ uint32_t sw128(uint32_t off) {
    return off ^ ((off >> 3) & 0x70u);
}

__device__ __forceinline__ uint32_t pack_h2(float x, float y) {
    __half2 h = __floats2half2_rn(x, y);
    return *reinterpret_cast<uint32_t*>(&h);
}

// pack two fp32 log2-scores to f16x2 and take exp2 of both halves (one MUFU op)
__device__ __forceinline__ uint32_t ex2_h2(float x, float y) {
    uint32_t p = pack_h2(x, y);
    uint32_t r;
    asm("ex2.approx.f16x2 %0, %1;" : "=r"(r) : "r"(p));
    return r;
}

#define QSCALE (0.125f * 1.44269504088896340736f)

// =================== fp32 -> fp16 conversion (x + 4 weights) ===============
#define N4X (MROWS*DIM/4)    // 2097152
#define N4W (DIM*DIM/4)      // 262144

__global__ void cvt_all(const float4* __restrict__ x,
                        const float4* __restrict__ w0, const float4* __restrict__ w1,
                        const float4* __restrict__ w2, const float4* __restrict__ w3,
                        uint2* __restrict__ Xh, uint2* __restrict__ Wh)
{
    int i = blockIdx.x * blockDim.x + threadIdx.x;
    float4 v;
    uint2* dst;
    if (i < N4X) {
        v = x[i];
        dst = Xh + i;
    } else {
        int j = i - N4X;
        int wsel = j >> 18;            // / N4W
        int k = j & (N4W - 1);
        const float4* w = (wsel == 0) ? w0 : (wsel == 1) ? w1
                        : (wsel == 2) ? w2 : w3;
        v = w[k];
        dst = Wh + ((size_t)wsel * N4W + k);
    }
    uint2 H;
    H.x = pack_h2(v.x, v.y);
    H.y = pack_h2(v.z, v.w);
    *dst = H;
}

// =================== rope cos/sin table ====================================
__global__ void rope_table(const int* __restrict__ pos, float2* __restrict__ RT)
{
    int idx = blockIdx.x * blockDim.x + threadIdx.x;
    if (idx >= SEQ * 32) return;
    int s = idx >> 5, i = idx & 31;
    float p = (float)pos[s];
    float freq = expf(-(float)(2*i) * (9.210340371976184f / 64.f));
    float sn, cs;
    sincosf(p * freq, &sn, &cs);
    RT[idx] = make_float2(cs, sn);
}

// ===== fused QKV / WO GEMM: 128x128 CTA, 4 warps x (64x64), 3-stage ========
#define G_A 0
#define G_B 16384
#define G_STAGE 32768
#define GEMM_SMEM (3*G_STAGE)        // 96KB
#define NCHUNK (DIM/64)              // 16

// acc[m][n][4]: m = 4 m16 tiles, n = 8 n8 frags (64 cols)
__device__ __forceinline__ void gemm_core(
    const __half* __restrict__ A, const __half* __restrict__ B,
    float acc[4][8][4], uint32_t sb, int tid)
{
    const int lane = tid & 31;
    const int wm   = (tid >> 5) >> 1;        // 0..1
    const int wn   = (tid >> 5) & 1;         // 0..1
    const int rin  = lane & 7;
    const int sel  = lane >> 3;

#define G_LOAD(stg, kc) do {                                                  \
    uint32_t _s = sb + (stg) * G_STAGE;                                       \
    const int _k0 = (kc) * 64;                                                \
    _Pragma("unroll")                                                         \
    for (int _j = 0; _j < 8; _j++) {                                          \
        int _c = tid + _j * 128;                                              \
        int _r = _c >> 3, _ch = _c & 7;                                       \
        uint32_t _sw = sw128((uint32_t)(_r * 128 + _ch * 16));                \
        cp_async16(_s + G_A + _sw, A + (size_t)_r * DIM + _k0 + _ch * 8);     \
        cp_async16(_s + G_B + _sw, B + (size_t)_r * DIM + _k0 + _ch * 8);     \
    }                                                                         \
    CP_COMMIT();                                                              \
} while (0)

    G_LOAD(0, 0);
    G_LOAD(1, 1);
    G_LOAD(2, 2);

    for (int kc = 0; kc < NCHUNK; kc++) {
        if (kc + 1 >= NCHUNK)      { CP_WAIT(0); }
        else if (kc + 2 >= NCHUNK) { CP_WAIT(1); }
        else                       { CP_WAIT(2); }
        __syncthreads();
        const uint32_t stg = sb + (kc % 3) * G_STAGE;

        #pragma unroll
        for (int ks = 0; ks < 4; ks++) {
            uint32_t av[4][4];
            #pragma unroll
            for (int m = 0; m < 4; m++) {
                int row = wm*64 + m*16 + (sel & 1)*8 + rin;
                int ch  = 2*ks + (sel >> 1);
                uint32_t sw = sw128((uint32_t)(row*128 + ch*16));
                ldsm_x4(av[m][0], av[m][1], av[m][2], av[m][3], stg + G_A + sw);
            }
            uint32_t bv[8][2];
            #pragma unroll
            for (int nf = 0; nf < 4; nf++) {
                int row = wn*64 + nf*16 + (sel >> 1)*8 + rin;
                int ch  = 2*ks + (sel & 1);
                uint32_t sw = sw128((uint32_t)(row*128 + ch*16));
                uint32_t r0, r1, r2, r3;
                ldsm_x4(r0, r1, r2, r3, stg + G_B + sw);
                bv[nf*2+0][0] = r0; bv[nf*2+0][1] = r1;
                bv[nf*2+1][0] = r2; bv[nf*2+1][1] = r3;
            }
            #pragma unroll
            for (int m = 0; m < 4; m++)
                #pragma unroll
                for (int n = 0; n < 8; n++)
                    mma_fp16(acc[m][n], av[m], bv[n]);
        }
        __syncthreads();
        if (kc + 3 < NCHUNK) G_LOAD(kc % 3, kc + 3);
    }
#undef G_LOAD
}

__global__ __launch_bounds__(128, 2)
void gemm_qkv(const __half* __restrict__ Xh, const __half* __restrict__ Wh,
              const float2* __restrict__ RT,
              __half* __restrict__ Qh, __half* __restrict__ Kh,
              __half* __restrict__ Vth)
{
    extern __shared__ char smem[];
    const uint32_t sb = smem_u32(smem);
    const int tid  = threadIdx.x;
    const int lane = tid & 31;
    const int wm   = (tid >> 5) >> 1;
    const int wn   = (tid >> 5) & 1;

    const int op  = blockIdx.x >> 3;       // 0:Q 1:K 2:V
    const int bxl = blockIdx.x & 7;

    const __half* A = Xh + (size_t)(blockIdx.y * 128) * DIM;
    const __half* B = Wh + (size_t)op * DIM * DIM + (size_t)(bxl * 128) * DIM;

    float acc[4][8][4];
    #pragma unroll
    for (int m = 0; m < 4; m++)
        #pragma unroll
        for (int n = 0; n < 8; n++)
            #pragma unroll
            for (int j = 0; j < 4; j++) acc[m][n][j] = 0.f;

    gemm_core(A, B, acc, sb, tid);

    const int lrow = wm * 64 + (lane >> 2);          // local row
    const int lcol = wn * 64 + (lane & 3) * 2;       // local col (even)

    if (op < 2) {
        // ---- Q/K epilogue: rope + fp16 store ----
        __half* dst = (op == 0) ? Qh : Kh;
        const float scale = (op == 0) ? QSCALE : 1.0f;
        #pragma unroll
        for (int m = 0; m < 4; m++) {
            #pragma unroll
            for (int n = 0; n < 8; n++) {
                int col = bxl * 128 + lcol + n * 8;
                int i   = (col >> 1) & 31;
                #pragma unroll
                for (int half_ = 0; half_ < 2; half_++) {
                    int row = blockIdx.y * 128 + lrow + m * 16 + half_ * 8;
                    int s   = row & (SEQ - 1);
                    float2 cs = RT[s * 32 + i];
                    float a0 = acc[m][n][half_*2 + 0];
                    float a1 = acc[m][n][half_*2 + 1];
                    float o0 = (a0 * cs.x - a1 * cs.y) * scale;
                    float o1 = (a0 * cs.y + a1 * cs.x) * scale;
                    *(uint32_t*)(dst + (size_t)row * DIM + col) = pack_h2(o0, o1);
                }
            }
        }
    } else {
        // ---- V epilogue: transpose via smem, write Vt[(b,h,d)][s] fp16 ----
        __half (*vt)[130] = (__half(*)[130])smem;
        #pragma unroll
        for (int m = 0; m < 4; m++) {
            #pragma unroll
            for (int n = 0; n < 8; n++) {
                int r = lrow + m * 16;
                int c = lcol + n * 8;
                *(uint32_t*)&vt[r][c]   = pack_h2(acc[m][n][0], acc[m][n][1]);
                *(uint32_t*)&vt[r+8][c] = pack_h2(acc[m][n][2], acc[m][n][3]);
            }
        }
        __syncthreads();
        const int bglob = (blockIdx.y * 128) >> 11;      // batch
        const int s0    = (blockIdx.y * 128) & (SEQ-1);
        #pragma unroll
        for (int it = 0; it < 16; it++) {
            int idx = tid + it * 128;        // 0..2047
            int dl  = idx >> 4;              // local dim 0..127
            int ch  = idx & 15;              // seq chunk (8 halves)
            __half tmp[8];
            #pragma unroll
            for (int k = 0; k < 8; k++) tmp[k] = vt[ch*8 + k][dl];
            int colg = bxl * 128 + dl;
            int h = colg >> 6, d = colg & 63;
            size_t dstoff = (size_t)((bglob * NHEAD + h) * 64 + d) * SEQ + s0 + ch * 8;
            *(uint4*)(Vth + dstoff) = *(uint4*)tmp;
        }
    }
}

// ================= WO GEMM: out = Oh * Wo^T (fp32 out) =====================
__global__ __launch_bounds__(128, 2)
void gemm_wo(const __half* __restrict__ Oh, const __half* __restrict__ Wh,
             float* __restrict__ C)
{
    extern __shared__ char smem[];
    const uint32_t sb = smem_u32(smem);
    const int tid  = threadIdx.x;
    const int lane = tid & 31;
    const int wm   = (tid >> 5) >> 1;
    const int wn   = (tid >> 5) & 1;

    const __half* A = Oh + (size_t)(blockIdx.y * 128) * DIM;
    const __half* B = Wh + (size_t)3 * DIM * DIM + (size_t)(blockIdx.x * 128) * DIM;

    float acc[4][8][4];
    #pragma unroll
    for (int m = 0; m < 4; m++)
        #pragma unroll
        for (int n = 0; n < 8; n++)
            #pragma unroll
            for (int j = 0; j < 4; j++) acc[m][n][j] = 0.f;

    gemm_core(A, B, acc, sb, tid);

    const int erow = blockIdx.y * 128 + wm * 64 + (lane >> 2);
    const int ecol = blockIdx.x * 128 + wn * 64 + (lane & 3) * 2;
    #pragma unroll
    for (int m = 0; m < 4; m++) {
        #pragma unroll
        for (int n = 0; n < 8; n++) {
            float* p0 = C + (size_t)(erow + m * 16) * DIM + ecol + n * 8;
            float* p1 = p0 + (size_t)8 * DIM;
            *(float2*)p0 = make_float2(acc[m][n][0], acc[m][n][1]);
            *(float2*)p1 = make_float2(acc[m][n][2], acc[m][n][3]);
        }
    }
}

// ====== flash attention: 128-row q tile, 3-stage KV, f16x2 exp2 ============
#define F_QH  0
#define F_STG 16384
#define F_K   0
#define F_V   8192
#define F_STAGE_BYTES 16384
#define FLASH_SMEM (16384 + 3*F_STAGE_BYTES)   // 64KB

__global__ __launch_bounds__(128, 2)
void flash_f16(const __half* __restrict__ Qh, const __half* __restrict__ Kh,
               const __half* __restrict__ Vth, __half* __restrict__ Oh)
{
    extern __shared__ char smem[];
    const uint32_t sb = smem_u32(smem);
    const int tid  = threadIdx.x;
    const int lane = tid & 31;
    const int w    = tid >> 5;
    const int g    = lane >> 2;
    const int t    = lane & 3;
    const int rin  = lane & 7;
    const int sel  = lane >> 3;

    const int bq = (SEQ/128 - 1) - blockIdx.x;   // heavy tiles first
    const int h  = blockIdx.y;
    const int b  = blockIdx.z;

    const int nblk = 2*bq + 2;

    // ---- prologue: Q tile (128 rows) + KV stages 0,1 ----
    {
        const size_t qbase = (size_t)(b*SEQ + bq*128);
        #pragma unroll
        for (int j = 0; j < 8; j++) {
            int c = tid + j*128;             // 0..1023
            int r = c >> 3, ch = c & 7;
            uint32_t sw = sw128((uint32_t)(r*128 + ch*16));
            cp_async16(sb + F_QH + sw, Qh + (qbase + r)*DIM + h*64 + ch*8);
        }
    }

#define LOAD_KV(stg, blk) do {                                                 \
    uint32_t _s = sb + F_STG + (stg)*F_STAGE_BYTES;                            \
    const int _k0 = (blk)*64;                                                  \
    _Pragma("unroll")                                                          \
    for (int _j = 0; _j < 4; _j++) {                                           \
        int _c = tid + _j*128;                                                 \
        int _r = _c >> 3, _ch = _c & 7;                                        \
        uint32_t _sw = sw128((uint32_t)(_r*128 + _ch*16));                     \
        cp_async16(_s + F_K + _sw,                                             \
                   Kh + (size_t)(b*SEQ + _k0 + _r)*DIM + h*64 + _ch*8);        \
        cp_async16(_s + F_V + _sw,                                             \
                   Vth + (size_t)((b*NHEAD + h)*64 + _r)*SEQ + _k0 + _ch*8);   \
    }                                                                          \
} while (0)

    LOAD_KV(0, 0);
    CP_COMMIT();            // group0: Q + KV0
    LOAD_KV(1, 1);
    CP_COMMIT();            // group1: KV1

    CP_WAIT(1);             // Q + KV0 ready
    __syncthreads();

    // ---- Q fragments: 2 m16 tiles x 4 k-chunks ----
    uint32_t qv[2][4][4];
    #pragma unroll
    for (int mt = 0; mt < 2; mt++) {
        #pragma unroll
        for (int kk = 0; kk < 4; kk++) {
            int row = w*32 + mt*16 + (sel & 1)*8 + rin;
            int ch  = 2*kk + (sel >> 1);
            uint32_t sw = sw128((uint32_t)(row*128 + ch*16));
            ldsm_x4(qv[mt][kk][0], qv[mt][kk][1], qv[mt][kk][2], qv[mt][kk][3],
                    sb + F_QH + sw);
        }
    }

    float O[2][8][4];
    #pragma unroll
    for (int mt = 0; mt < 2; mt++)
        #pragma unroll
        for (int f = 0; f < 8; f++)
            #pragma unroll
            for (int j = 0; j < 4; j++) O[mt][f][j] = 0.f;
    float L[2][4] = {{0.f,0.f,0.f,0.f},{0.f,0.f,0.f,0.f}};
    const uint32_t ones2 = 0x3C003C00u;
    const uint32_t ones_b[2] = {ones2, ones2};

    for (int i = 0; i < nblk; i++) {
        if (i > 0) {
            if (i == nblk - 1) { CP_WAIT(0); } else { CP_WAIT(1); }
            __syncthreads();
        }
        if (i + 2 < nblk) {
            LOAD_KV((i + 2) % 3, i + 2);
            CP_COMMIT();
        }
        const uint32_t kb = sb + F_STG + (i % 3)*F_STAGE_BYTES;

        // ---- S = Q * K^T for both m-tiles (K frags loaded once) ----
        float S[2][8][4];
        #pragma unroll
        for (int mt = 0; mt < 2; mt++)
            #pragma unroll
            for (int f = 0; f < 8; f++)
                #pragma unroll
                for (int j = 0; j < 4; j++) S[mt][f][j] = 0.f;

        #pragma unroll
        for (int kk = 0; kk < 4; kk++) {
            #pragma unroll
            for (int nfp = 0; nfp < 4; nfp++) {
                int row = nfp*16 + (sel >> 1)*8 + rin;
                int ch  = 2*kk + (sel & 1);
                uint32_t sw = sw128((uint32_t)(row*128 + ch*16));
                uint32_t k0r, k1r, k2r, k3r;
                ldsm_x4(k0r, k1r, k2r, k3r, kb + F_K + sw);
                uint32_t b0[2] = {k0r, k1r}, b1[2] = {k2r, k3r};
                #pragma unroll
                for (int mt = 0; mt < 2; mt++) {
                    mma_fp16(S[mt][nfp*2],   qv[mt][kk], b0);
                    mma_fp16(S[mt][nfp*2+1], qv[mt][kk], b1);
                }
            }
        }

        // ---- causal mask (last two key blocks cross the diagonal) ----
        if (i >= nblk - 2) {
            #pragma unroll
            for (int mt = 0; mt < 2; mt++) {
                int r0 = w*32 + mt*16 + g;       // q row rel. to tile start
                int r1 = r0 + 8;
                #pragma unroll
                for (int f = 0; f < 8; f++) {
                    int kl = i*64 + f*8 + 2*t - bq*128;  // key rel. to tile start
                    if (kl     > r0) S[mt][f][0] = -1e30f;
                    if (kl + 1 > r0) S[mt][f][1] = -1e30f;
                    if (kl     > r1) S[mt][f][2] = -1e30f;
                    if (kl + 1 > r1) S[mt][f][3] = -1e30f;
                }
            }
        }

        // ---- O += exp2(S)*V ; L += exp2(S)*ones  (exp2 fused into pack) ----
        #pragma unroll
        for (int kk = 0; kk < 4; kk++) {
            uint32_t ap[2][4];
            #pragma unroll
            for (int mt = 0; mt < 2; mt++) {
                ap[mt][0] = ex2_h2(S[mt][2*kk][0],   S[mt][2*kk][1]);
                ap[mt][1] = ex2_h2(S[mt][2*kk][2],   S[mt][2*kk][3]);
                ap[mt][2] = ex2_h2(S[mt][2*kk+1][0], S[mt][2*kk+1][1]);
                ap[mt][3] = ex2_h2(S[mt][2*kk+1][2], S[mt][2*kk+1][3]);
                mma_fp16(L[mt], ap[mt], ones_b);
            }
            #pragma unroll
            for (int nfp = 0; nfp < 4; nfp++) {
                int row = nfp*16 + (sel >> 1)*8 + rin;
                int ch  = 2*kk + (sel & 1);
                uint32_t sw = sw128((uint32_t)(row*128 + ch*16));
                uint32_t v0, v1, v2, v3;
                ldsm_x4(v0, v1, v2, v3, kb + F_V + sw);
                uint32_t b0[2] = {v0, v1}, b1[2] = {v2, v3};
                #pragma unroll
                for (int mt = 0; mt < 2; mt++) {
                    mma_fp16(O[mt][nfp*2],   ap[mt], b0);
                    mma_fp16(O[mt][nfp*2+1], ap[mt], b1);
                }
            }
        }
    }

    // ---- epilogue: normalize + fp16 store ----
    #pragma unroll
    for (int mt = 0; mt < 2; mt++) {
        const float inv0 = 1.0f / L[mt][0];
        const float inv1 = 1.0f / L[mt][2];
        const size_t row0 = (size_t)(b*SEQ + bq*128 + w*32 + mt*16 + g);
        const size_t row1 = row0 + 8;
        #pragma unroll
        for (int f = 0; f < 8; f++) {
            int col = h*64 + f*8 + 2*t;
            *(uint32_t*)(Oh + row0*DIM + col) = pack_h2(O[mt][f][0]*inv0, O[mt][f][1]*inv0);
            *(uint32_t*)(Oh + row1*DIM + col) = pack_h2(O[mt][f][2]*inv1, O[mt][f][3]*inv1);
        }
    }
}

// ---------------- launch ---------------------------------------------------
extern "C" void kernel_launch(void* const* d_in, const int* in_sizes, int n_in,
                              void* d_out, int out_size)
{
    const float* x   = (const float*)d_in[0];
    const int*   pos = (const int*)  d_in[1];
    const float* wq  = (const float*)d_in[2];
    const float* wk  = (const float*)d_in[3];
    const float* wv  = (const float*)d_in[4];
    const float* wo  = (const float*)d_in[5];
    float* out = (float*)d_out;

    __half *Xh, *Wh, *Qh, *Kh, *Vth, *Oh;
    float2* RT;
    cudaGetSymbolAddress((void**)&Xh, g_Xh);
    cudaGetSymbolAddress((void**)&Wh, g_Wh);
    cudaGetSymbolAddress((void**)&Qh, g_Qh);
    cudaGetSymbolAddress((void**)&Kh, g_Kh);
    cudaGetSymbolAddress((void**)&Vth, g_Vth);
    cudaGetSymbolAddress((void**)&Oh, g_Oh);
    cudaGetSymbolAddress((void**)&RT, g_RT);

    cudaFuncSetAttribute(gemm_qkv,
                         cudaFuncAttributeMaxDynamicSharedMemorySize, GEMM_SMEM);
    cudaFuncSetAttribute(gemm_wo,
                         cudaFuncAttributeMaxDynamicSharedMemorySize, GEMM_SMEM);
    cudaFuncSetAttribute(flash_f16,
                         cudaFuncAttributeMaxDynamicSharedMemorySize, FLASH_SMEM);

    const int ntot = N4X + 4 * N4W;
    cvt_all<<<(ntot + 255)/256, 256>>>((const float4*)x,
        (const float4*)wq, (const float4*)wk, (const float4*)wv, (const float4*)wo,
        (uint2*)Xh, (uint2*)Wh);

    rope_table<<<(SEQ*32 + 255)/256, 256>>>(pos, RT);

    gemm_qkv<<<dim3(24, MROWS/128), 128, GEMM_SMEM>>>(Xh, Wh, RT, Qh, Kh, Vth);

    flash_f16<<<dim3(SEQ/128, NHEAD, BATCH), 128, FLASH_SMEM>>>(Qh, Kh, Vth, Oh);

    gemm_wo<<<dim3(DIM/128, MROWS/128), 128, GEMM_SMEM>>>(Oh, Wh, out);
}

// round 14
// speedup vs baseline: 1.4604x; 1.4604x over previous
#include <cuda_runtime.h>
#include <cuda_fp16.h>
#include <math.h>
#include <cstdint>

#define BATCH 4
#define SEQ   2048
#define DIM   1024
#define NHEAD 16
#define DH    64
#define MROWS (BATCH*SEQ)   // 8192

// ---------------- scratch (device globals: no allocation allowed) ----------
__device__ __half g_Xh[(size_t)MROWS*DIM];
__device__ __half g_Wh[(size_t)4*DIM*DIM];
__device__ __half g_Qh[(size_t)MROWS*DIM];
__device__ __half g_Kh[(size_t)MROWS*DIM];
__device__ __half g_Vth[(size_t)MROWS*DIM];  // [b][h][dim][seq]
__device__ __half g_Oh[(size_t)MROWS*DIM];
__device__ float2 g_RT[(size_t)SEQ*32];      // rope table: cos,sin per (s, i)

// ========================= helpers ========================================
__device__ __forceinline__ uint32_t smem_u32(const void* p) {
    uint32_t a;
    asm("{ .reg .u64 t; cvta.to.shared.u64 t, %1; cvt.u32.u64 %0, t; }"
        : "=r"(a) : "l"(p));
    return a;
}

__device__ __forceinline__ void cp_async16(uint32_t dst, const void* src) {
    asm volatile("cp.async.cg.shared.global [%0], [%1], 16;"
                 :: "r"(dst), "l"(src) : "memory");
}
#define CP_COMMIT() asm volatile("cp.async.commit_group;" ::: "memory")
#define CP_WAIT(n)  asm volatile("cp.async.wait_group %0;" :: "n"(n) : "memory")

__device__ __forceinline__ void ldsm_x4(uint32_t& r0, uint32_t& r1,
                                        uint32_t& r2, uint32_t& r3, uint32_t a) {
    asm volatile("ldmatrix.sync.aligned.m8n8.x4.shared.b16 {%0,%1,%2,%3}, [%4];"
                 : "=r"(r0), "=r"(r1), "=r"(r2), "=r"(r3) : "r"(a));
}

__device__ __forceinline__ void mma_fp16(float* d, const uint32_t* a,
                                         const uint32_t* b) {
    asm volatile("mma.sync.aligned.m16n8k16.row.col.f32.f16.f16.f32 "
                 "{%0,%1,%2,%3}, {%4,%5,%6,%7}, {%8,%9}, {%0,%1,%2,%3};"
                 : "+f"(d[0]), "+f"(d[1]), "+f"(d[2]), "+f"(d[3])
                 : "r"(a[0]), "r"(a[1]), "r"(a[2]), "r"(a[3]),
                   "r"(b[0]), "r"(b[1]));
}

__device__ __forceinline__ uint32_t sw128(uint32_t off) {
    return off ^ ((off >> 3) & 0x70u);
}

__device__ __forceinline__ uint32_t pack_h2(float x, float y) {
    __half2 h = __floats2half2_rn(x, y);
    return *reinterpret_cast<uint32_t*>(&h);
}

// pack two fp32 log2-scores to f16x2 and take exp2 of both halves (one MUFU op)
__device__ __forceinline__ uint32_t ex2_h2(float x, float y) {
    uint32_t p = pack_h2(x, y);
    uint32_t r;
    asm("ex2.approx.f16x2 %0, %1;" : "=r"(r) : "r"(p));
    return r;
}

#define QSCALE (0.125f * 1.44269504088896340736f)

// =================== fp32 -> fp16 conversion (x + 4 weights) ===============
#define N4X (MROWS*DIM/4)    // 2097152
#define N4W (DIM*DIM/4)      // 262144

__global__ void cvt_all(const float4* __restrict__ x,
                        const float4* __restrict__ w0, const float4* __restrict__ w1,
                        const float4* __restrict__ w2, const float4* __restrict__ w3,
                        uint2* __restrict__ Xh, uint2* __restrict__ Wh)
{
    int i = blockIdx.x * blockDim.x + threadIdx.x;
    float4 v;
    uint2* dst;
    if (i < N4X) {
        v = x[i];
        dst = Xh + i;
    } else {
        int j = i - N4X;
        int wsel = j >> 18;            // / N4W
        int k = j & (N4W - 1);
        const float4* w = (wsel == 0) ? w0 : (wsel == 1) ? w1
                        : (wsel == 2) ? w2 : w3;
        v = w[k];
        dst = Wh + ((size_t)wsel * N4W + k);
    }
    uint2 H;
    H.x = pack_h2(v.x, v.y);
    H.y = pack_h2(v.z, v.w);
    *dst = H;
}

// =================== rope cos/sin table ====================================
__global__ void rope_table(const int* __restrict__ pos, float2* __restrict__ RT)
{
    int idx = blockIdx.x * blockDim.x + threadIdx.x;
    if (idx >= SEQ * 32) return;
    int s = idx >> 5, i = idx & 31;
    float p = (float)pos[s];
    float freq = expf(-(float)(2*i) * (9.210340371976184f / 64.f));
    float sn, cs;
    sincosf(p * freq, &sn, &cs);
    RT[idx] = make_float2(cs, sn);
}

// ===== QKV / WO GEMM: 128x128 CTA, 8 warps x (64x32), 3-stage cp.async =====
#define G_A 0
#define G_B 16384
#define G_STAGE 32768
#define GEMM_SMEM (3*G_STAGE)        // 96KB
#define NCHUNK (DIM/64)              // 16

__device__ __forceinline__ void gemm_core(
    const __half* __restrict__ A, const __half* __restrict__ B,
    float acc[4][4][4], uint32_t sb, int tid)
{
    const int lane = tid & 31;
    const int wm   = (tid >> 5) >> 2;        // 0..1
    const int wn   = (tid >> 5) & 3;         // 0..3
    const int rin  = lane & 7;
    const int sel  = lane >> 3;

#define G_LOAD(stg, kc) do {                                                  \
    uint32_t _s = sb + (stg) * G_STAGE;                                       \
    const int _k0 = (kc) * 64;                                                \
    _Pragma("unroll")                                                         \
    for (int _j = 0; _j < 4; _j++) {                                          \
        int _c = tid + _j * 256;                                              \
        int _r = _c >> 3, _ch = _c & 7;                                       \
        uint32_t _sw = sw128((uint32_t)(_r * 128 + _ch * 16));                \
        cp_async16(_s + G_A + _sw, A + (size_t)_r * DIM + _k0 + _ch * 8);     \
        cp_async16(_s + G_B + _sw, B + (size_t)_r * DIM + _k0 + _ch * 8);     \
    }                                                                         \
    CP_COMMIT();                                                              \
} while (0)

    G_LOAD(0, 0);
    G_LOAD(1, 1);
    G_LOAD(2, 2);

    for (int kc = 0; kc < NCHUNK; kc++) {
        if (kc + 1 >= NCHUNK)      { CP_WAIT(0); }
        else if (kc + 2 >= NCHUNK) { CP_WAIT(1); }
        else                       { CP_WAIT(2); }
        __syncthreads();
        const uint32_t stg = sb + (kc % 3) * G_STAGE;

        #pragma unroll
        for (int ks = 0; ks < 4; ks++) {
            uint32_t av[4][4];
            #pragma unroll
            for (int m = 0; m < 4; m++) {
                int row = wm*64 + m*16 + (sel & 1)*8 + rin;
                int ch  = 2*ks + (sel >> 1);
                uint32_t sw = sw128((uint32_t)(row*128 + ch*16));
                ldsm_x4(av[m][0], av[m][1], av[m][2], av[m][3], stg + G_A + sw);
            }
            uint32_t bv[4][2];
            #pragma unroll
            for (int nf = 0; nf < 2; nf++) {
                int row = wn*32 + nf*16 + (sel >> 1)*8 + rin;
                int ch  = 2*ks + (sel & 1);
                uint32_t sw = sw128((uint32_t)(row*128 + ch*16));
                uint32_t r0, r1, r2, r3;
                ldsm_x4(r0, r1, r2, r3, stg + G_B + sw);
                bv[nf*2+0][0] = r0; bv[nf*2+0][1] = r1;
                bv[nf*2+1][0] = r2; bv[nf*2+1][1] = r3;
            }
            #pragma unroll
            for (int m = 0; m < 4; m++)
                #pragma unroll
                for (int n = 0; n < 4; n++)
                    mma_fp16(acc[m][n], av[m], bv[n]);
        }
        __syncthreads();
        if (kc + 3 < NCHUNK) G_LOAD(kc % 3, kc + 3);
    }
#undef G_LOAD
}

__global__ __launch_bounds__(256, 2)
void gemm_qkv(const __half* __restrict__ Xh, const __half* __restrict__ Wh,
              const float2* __restrict__ RT,
              __half* __restrict__ Qh, __half* __restrict__ Kh,
              __half* __restrict__ Vth)
{
    extern __shared__ char smem[];
    const uint32_t sb = smem_u32(smem);
    const int tid  = threadIdx.x;
    const int lane = tid & 31;
    const int wm   = (tid >> 5) >> 2;
    const int wn   = (tid >> 5) & 3;

    const int op  = blockIdx.x >> 3;       // 0:Q 1:K 2:V
    const int bxl = blockIdx.x & 7;

    const __half* A = Xh + (size_t)(blockIdx.y * 128) * DIM;
    const __half* B = Wh + (size_t)op * DIM * DIM + (size_t)(bxl * 128) * DIM;

    float acc[4][4][4];
    #pragma unroll
    for (int m = 0; m < 4; m++)
        #pragma unroll
        for (int n = 0; n < 4; n++)
            #pragma unroll
            for (int j = 0; j < 4; j++) acc[m][n][j] = 0.f;

    gemm_core(A, B, acc, sb, tid);

    const int lrow = wm * 64 + (lane >> 2);          // local row
    const int lcol = wn * 32 + (lane & 3) * 2;       // local col (even)

    if (op < 2) {
        // ---- Q/K epilogue: rope + fp16 store ----
        __half* dst = (op == 0) ? Qh : Kh;
        const float scale = (op == 0) ? QSCALE : 1.0f;
        #pragma unroll
        for (int m = 0; m < 4; m++) {
            #pragma unroll
            for (int n = 0; n < 4; n++) {
                int col = bxl * 128 + lcol + n * 8;
                int i   = (col >> 1) & 31;
                #pragma unroll
                for (int half_ = 0; half_ < 2; half_++) {
                    int row = blockIdx.y * 128 + lrow + m * 16 + half_ * 8;
                    int s   = row & (SEQ - 1);
                    float2 cs = RT[s * 32 + i];
                    float a0 = acc[m][n][half_*2 + 0];
                    float a1 = acc[m][n][half_*2 + 1];
                    float o0 = (a0 * cs.x - a1 * cs.y) * scale;
                    float o1 = (a0 * cs.y + a1 * cs.x) * scale;
                    *(uint32_t*)(dst + (size_t)row * DIM + col) = pack_h2(o0, o1);
                }
            }
        }
    } else {
        // ---- V epilogue: transpose via smem, write Vt[(b,h,d)][s] fp16 ----
        __half (*vt)[130] = (__half(*)[130])smem;
        #pragma unroll
        for (int m = 0; m < 4; m++) {
            #pragma unroll
            for (int n = 0; n < 4; n++) {
                int r = lrow + m * 16;
                int c = lcol + n * 8;
                *(uint32_t*)&vt[r][c]   = pack_h2(acc[m][n][0], acc[m][n][1]);
                *(uint32_t*)&vt[r+8][c] = pack_h2(acc[m][n][2], acc[m][n][3]);
            }
        }
        __syncthreads();
        const int bglob = (blockIdx.y * 128) >> 11;      // batch
        const int s0    = (blockIdx.y * 128) & (SEQ-1);
        #pragma unroll
        for (int it = 0; it < 8; it++) {
            int idx = tid + it * 256;        // 0..2047
            int dl  = idx >> 4;              // local dim 0..127
            int ch  = idx & 15;              // seq chunk (8 halves)
            __half tmp[8];
            #pragma unroll
            for (int k = 0; k < 8; k++) tmp[k] = vt[ch*8 + k][dl];
            int colg = bxl * 128 + dl;
            int h = colg >> 6, d = colg & 63;
            size_t dstoff = (size_t)((bglob * NHEAD + h) * 64 + d) * SEQ + s0 + ch * 8;
            *(uint4*)(Vth + dstoff) = *(uint4*)tmp;
        }
    }
}

// ================= WO GEMM: out = Oh * Wo^T (fp32 out) =====================
__global__ __launch_bounds__(256, 2)
void gemm_wo(const __half* __restrict__ Oh, const __half* __restrict__ Wh,
             float* __restrict__ C)
{
    extern __shared__ char smem[];
    const uint32_t sb = smem_u32(smem);
    const int tid  = threadIdx.x;
    const int lane = tid & 31;
    const int wm   = (tid >> 5) >> 2;
    const int wn   = (tid >> 5) & 3;

    const __half* A = Oh + (size_t)(blockIdx.y * 128) * DIM;
    const __half* B = Wh + (size_t)3 * DIM * DIM + (size_t)(blockIdx.x * 128) * DIM;

    float acc[4][4][4];
    #pragma unroll
    for (int m = 0; m < 4; m++)
        #pragma unroll
        for (int n = 0; n < 4; n++)
            #pragma unroll
            for (int j = 0; j < 4; j++) acc[m][n][j] = 0.f;

    gemm_core(A, B, acc, sb, tid);

    const int erow = blockIdx.y * 128 + wm * 64 + (lane >> 2);
    const int ecol = blockIdx.x * 128 + wn * 32 + (lane & 3) * 2;
    #pragma unroll
    for (int m = 0; m < 4; m++) {
        #pragma unroll
        for (int n = 0; n < 4; n++) {
            float* p0 = C + (size_t)(erow + m * 16) * DIM + ecol + n * 8;
            float* p1 = p0 + (size_t)8 * DIM;
            *(float2*)p0 = make_float2(acc[m][n][0], acc[m][n][1]);
            *(float2*)p1 = make_float2(acc[m][n][2], acc[m][n][3]);
        }
    }
}

// ====== flash attention: 128-row q tile, 3-stage KV, f16x2 exp2 ============
#define F_QH  0
#define F_STG 16384
#define F_K   0
#define F_V   8192
#define F_STAGE_BYTES 16384
#define FLASH_SMEM (16384 + 3*F_STAGE_BYTES)   // 64KB

__global__ __launch_bounds__(128, 2)
void flash_f16(const __half* __restrict__ Qh, const __half* __restrict__ Kh,
               const __half* __restrict__ Vth, __half* __restrict__ Oh)
{
    extern __shared__ char smem[];
    const uint32_t sb = smem_u32(smem);
    const int tid  = threadIdx.x;
    const int lane = tid & 31;
    const int w    = tid >> 5;
    const int g    = lane >> 2;
    const int t    = lane & 3;
    const int rin  = lane & 7;
    const int sel  = lane >> 3;

    const int bq = (SEQ/128 - 1) - blockIdx.x;   // heavy tiles first
    const int h  = blockIdx.y;
    const int b  = blockIdx.z;

    const int nblk = 2*bq + 2;

    // ---- prologue: Q tile (128 rows) + KV stages 0,1 ----
    {
        const size_t qbase = (size_t)(b*SEQ + bq*128);
        #pragma unroll
        for (int j = 0; j < 8; j++) {
            int c = tid + j*128;             // 0..1023
            int r = c >> 3, ch = c & 7;
            uint32_t sw = sw128((uint32_t)(r*128 + ch*16));
            cp_async16(sb + F_QH + sw, Qh + (qbase + r)*DIM + h*64 + ch*8);
        }
    }

#define LOAD_KV(stg, blk) do {                                                 \
    uint32_t _s = sb + F_STG + (stg)*F_STAGE_BYTES;                            \
    const int _k0 = (blk)*64;                                                  \
    _Pragma("unroll")                                                          \
    for (int _j = 0; _j < 4; _j++) {                                           \
        int _c = tid + _j*128;                                                 \
        int _r = _c >> 3, _ch = _c & 7;                                        \
        uint32_t _sw = sw128((uint32_t)(_r*128 + _ch*16));                     \
        cp_async16(_s + F_K + _sw,                                             \
                   Kh + (size_t)(b*SEQ + _k0 + _r)*DIM + h*64 + _ch*8);        \
        cp_async16(_s + F_V + _sw,                                             \
                   Vth + (size_t)((b*NHEAD + h)*64 + _r)*SEQ + _k0 + _ch*8);   \
    }                                                                          \
} while (0)

    LOAD_KV(0, 0);
    CP_COMMIT();            // group0: Q + KV0
    LOAD_KV(1, 1);
    CP_COMMIT();            // group1: KV1

    CP_WAIT(1);             // Q + KV0 ready
    __syncthreads();

    // ---- Q fragments: 2 m16 tiles x 4 k-chunks ----
    uint32_t qv[2][4][4];
    #pragma unroll
    for (int mt = 0; mt < 2; mt++) {
        #pragma unroll
        for (int kk = 0; kk < 4; kk++) {
            int row = w*32 + mt*16 + (sel & 1)*8 + rin;
            int ch  = 2*kk + (sel >> 1);
            uint32_t sw = sw128((uint32_t)(row*128 + ch*16));
            ldsm_x4(qv[mt][kk][0], qv[mt][kk][1], qv[mt][kk][2], qv[mt][kk][3],
                    sb + F_QH + sw);
        }
    }

    float O[2][8][4];
    #pragma unroll
    for (int mt = 0; mt < 2; mt++)
        #pragma unroll
        for (int f = 0; f < 8; f++)
            #pragma unroll
            for (int j = 0; j < 4; j++) O[mt][f][j] = 0.f;
    float L[2][4] = {{0.f,0.f,0.f,0.f},{0.f,0.f,0.f,0.f}};
    const uint32_t ones2 = 0x3C003C00u;
    const uint32_t ones_b[2] = {ones2, ones2};

    for (int i = 0; i < nblk; i++) {
        if (i > 0) {
            if (i == nblk - 1) { CP_WAIT(0); } else { CP_WAIT(1); }
            __syncthreads();
        }
        if (i + 2 < nblk) {
            LOAD_KV((i + 2) % 3, i + 2);
            CP_COMMIT();
        }
        const uint32_t kb = sb + F_STG + (i % 3)*F_STAGE_BYTES;

        // ---- S = Q * K^T for both m-tiles (K frags loaded once) ----
        float S[2][8][4];
        #pragma unroll
        for (int mt = 0; mt < 2; mt++)
            #pragma unroll
            for (int f = 0; f < 8; f++)
                #pragma unroll
                for (int j = 0; j < 4; j++) S[mt][f][j] = 0.f;

        #pragma unroll
        for (int kk = 0; kk < 4; kk++) {
            #pragma unroll
            for (int nfp = 0; nfp < 4; nfp++) {
                int row = nfp*16 + (sel >> 1)*8 + rin;
                int ch  = 2*kk + (sel & 1);
                uint32_t sw = sw128((uint32_t)(row*128 + ch*16));
                uint32_t k0r, k1r, k2r, k3r;
                ldsm_x4(k0r, k1r, k2r, k3r, kb + F_K + sw);
                uint32_t b0[2] = {k0r, k1r}, b1[2] = {k2r, k3r};
                #pragma unroll
                for (int mt = 0; mt < 2; mt++) {
                    mma_fp16(S[mt][nfp*2],   qv[mt][kk], b0);
                    mma_fp16(S[mt][nfp*2+1], qv[mt][kk], b1);
                }
            }
        }

        // ---- causal mask (last two key blocks cross the diagonal) ----
        if (i >= nblk - 2) {
            #pragma unroll
            for (int mt = 0; mt < 2; mt++) {
                int r0 = w*32 + mt*16 + g;       // q row rel. to tile start
                int r1 = r0 + 8;
                #pragma unroll
                for (int f = 0; f < 8; f++) {
                    int kl = i*64 + f*8 + 2*t - bq*128;  // key rel. to tile start
                    if (kl     > r0) S[mt][f][0] = -1e30f;
                    if (kl + 1 > r0) S[mt][f][1] = -1e30f;
                    if (kl     > r1) S[mt][f][2] = -1e30f;
                    if (kl + 1 > r1) S[mt][f][3] = -1e30f;
                }
            }
        }

        // ---- O += exp2(S)*V ; L += exp2(S)*ones  (exp2 fused into pack) ----
        #pragma unroll
        for (int kk = 0; kk < 4; kk++) {
            uint32_t ap[2][4];
            #pragma unroll
            for (int mt = 0; mt < 2; mt++) {
                ap[mt][0] = ex2_h2(S[mt][2*kk][0],   S[mt][2*kk][1]);
                ap[mt][1] = ex2_h2(S[mt][2*kk][2],   S[mt][2*kk][3]);
                ap[mt][2] = ex2_h2(S[mt][2*kk+1][0], S[mt][2*kk+1][1]);
                ap[mt][3] = ex2_h2(S[mt][2*kk+1][2], S[mt][2*kk+1][3]);
                mma_fp16(L[mt], ap[mt], ones_b);
            }
            #pragma unroll
            for (int nfp = 0; nfp < 4; nfp++) {
                int row = nfp*16 + (sel >> 1)*8 + rin;
                int ch  = 2*kk + (sel & 1);
                uint32_t sw = sw128((uint32_t)(row*128 + ch*16));
                uint32_t v0, v1, v2, v3;
                ldsm_x4(v0, v1, v2, v3, kb + F_V + sw);
                uint32_t b0[2] = {v0, v1}, b1[2] = {v2, v3};
                #pragma unroll
                for (int mt = 0; mt < 2; mt++) {
                    mma_fp16(O[mt][nfp*2],   ap[mt], b0);
                    mma_fp16(O[mt][nfp*2+1], ap[mt], b1);
                }
            }
        }
    }

    // ---- epilogue: normalize + fp16 store ----
    #pragma unroll
    for (int mt = 0; mt < 2; mt++) {
        const float inv0 = 1.0f / L[mt][0];
        const float inv1 = 1.0f / L[mt][2];
        const size_t row0 = (size_t)(b*SEQ + bq*128 + w*32 + mt*16 + g);
        const size_t row1 = row0 + 8;
        #pragma unroll
        for (int f = 0; f < 8; f++) {
            int col = h*64 + f*8 + 2*t;
            *(uint32_t*)(Oh + row0*DIM + col) = pack_h2(O[mt][f][0]*inv0, O[mt][f][1]*inv0);
            *(uint32_t*)(Oh + row1*DIM + col) = pack_h2(O[mt][f][2]*inv1, O[mt][f][3]*inv1);
        }
    }
}

// ---------------- launch ---------------------------------------------------
extern "C" void kernel_launch(void* const* d_in, const int* in_sizes, int n_in,
                              void* d_out, int out_size)
{
    const float* x   = (const float*)d_in[0];
    const int*   pos = (const int*)  d_in[1];
    const float* wq  = (const float*)d_in[2];
    const float* wk  = (const float*)d_in[3];
    const float* wv  = (const float*)d_in[4];
    const float* wo  = (const float*)d_in[5];
    float* out = (float*)d_out;

    __half *Xh, *Wh, *Qh, *Kh, *Vth, *Oh;
    float2* RT;
    cudaGetSymbolAddress((void**)&Xh, g_Xh);
    cudaGetSymbolAddress((void**)&Wh, g_Wh);
    cudaGetSymbolAddress((void**)&Qh, g_Qh);
    cudaGetSymbolAddress((void**)&Kh, g_Kh);
    cudaGetSymbolAddress((void**)&Vth, g_Vth);
    cudaGetSymbolAddress((void**)&Oh, g_Oh);
    cudaGetSymbolAddress((void**)&RT, g_RT);

    cudaFuncSetAttribute(gemm_qkv,
                         cudaFuncAttributeMaxDynamicSharedMemorySize, GEMM_SMEM);
    cudaFuncSetAttribute(gemm_wo,
                         cudaFuncAttributeMaxDynamicSharedMemorySize, GEMM_SMEM);
    cudaFuncSetAttribute(flash_f16,
                         cudaFuncAttributeMaxDynamicSharedMemorySize, FLASH_SMEM);

    const int ntot = N4X + 4 * N4W;
    cvt_all<<<(ntot + 255)/256, 256>>>((const float4*)x,
        (const float4*)wq, (const float4*)wk, (const float4*)wv, (const float4*)wo,
        (uint2*)Xh, (uint2*)Wh);

    rope_table<<<(SEQ*32 + 255)/256, 256>>>(pos, RT);

    gemm_qkv<<<dim3(24, MROWS/128), 256, GEMM_SMEM>>>(Xh, Wh, RT, Qh, Kh, Vth);

    flash_f16<<<dim3(SEQ/128, NHEAD, BATCH), 128, FLASH_SMEM>>>(Qh, Kh, Vth, Oh);

    gemm_wo<<<dim3(DIM/128, MROWS/128), 256, GEMM_SMEM>>>(Oh, Wh, out);
}

// round 15
// speedup vs baseline: 1.5099x; 1.0339x over previous
#include <cuda_runtime.h>
#include <cuda_fp16.h>
#include <math.h>
#include <cstdint>

#define BATCH 4
#define SEQ   2048
#define DIM   1024
#define NHEAD 16
#define DH    64
#define MROWS (BATCH*SEQ)   // 8192

// ---------------- scratch (device globals: no allocation allowed) ----------
__device__ __half g_Xh[(size_t)MROWS*DIM];
__device__ __half g_Wh[(size_t)4*DIM*DIM];
__device__ __half g_Qh[(size_t)MROWS*DIM];
__device__ __half g_Kh[(size_t)MROWS*DIM];
__device__ __half g_Vth[(size_t)MROWS*DIM];  // [b][h][dim][seq]
__device__ __half g_Oh[(size_t)MROWS*DIM];
__device__ float2 g_RT[(size_t)SEQ*32];      // rope table: cos,sin per (s, i)

// ========================= helpers ========================================
__device__ __forceinline__ uint32_t smem_u32(const void* p) {
    uint32_t a;
    asm("{ .reg .u64 t; cvta.to.shared.u64 t, %1; cvt.u32.u64 %0, t; }"
        : "=r"(a) : "l"(p));
    return a;
}

__device__ __forceinline__ void cp_async16(uint32_t dst, const void* src) {
    asm volatile("cp.async.cg.shared.global [%0], [%1], 16;"
                 :: "r"(dst), "l"(src) : "memory");
}
#define CP_COMMIT() asm volatile("cp.async.commit_group;" ::: "memory")
#define CP_WAIT(n)  asm volatile("cp.async.wait_group %0;" :: "n"(n) : "memory")

__device__ __forceinline__ void ldsm_x4(uint32_t& r0, uint32_t& r1,
                                        uint32_t& r2, uint32_t& r3, uint32_t a) {
    asm volatile("ldmatrix.sync.aligned.m8n8.x4.shared.b16 {%0,%1,%2,%3}, [%4];"
                 : "=r"(r0), "=r"(r1), "=r"(r2), "=r"(r3) : "r"(a));
}

__device__ __forceinline__ void mma_fp16(float* d, const uint32_t* a,
                                         const uint32_t* b) {
    asm volatile("mma.sync.aligned.m16n8k16.row.col.f32.f16.f16.f32 "
                 "{%0,%1,%2,%3}, {%4,%5,%6,%7}, {%8,%9}, {%0,%1,%2,%3};"
                 : "+f"(d[0]), "+f"(d[1]), "+f"(d[2]), "+f"(d[3])
                 : "r"(a[0]), "r"(a[1]), "r"(a[2]), "r"(a[3]),
                   "r"(b[0]), "r"(b[1]));
}

__device__ __forceinline__ uint32_t sw128(uint32_t off) {
    return off ^ ((off >> 3) & 0x70u);
}

__device__ __forceinline__ uint32_t pack_h2(float x, float y) {
    __half2 h = __floats2half2_rn(x, y);
    return *reinterpret_cast<uint32_t*>(&h);
}

// pack two fp32 log2-scores to f16x2 and take exp2 of both halves (one MUFU op)
__device__ __forceinline__ uint32_t ex2_h2(float x, float y) {
    uint32_t p = pack_h2(x, y);
    uint32_t r;
    asm("ex2.approx.f16x2 %0, %1;" : "=r"(r) : "r"(p));
    return r;
}

#define QSCALE (0.125f * 1.44269504088896340736f)

// =================== fp32 -> fp16 conversion (x + 4 weights) ===============
#define N4X (MROWS*DIM/4)    // 2097152
#define N4W (DIM*DIM/4)      // 262144

__global__ void cvt_all(const float4* __restrict__ x,
                        const float4* __restrict__ w0, const float4* __restrict__ w1,
                        const float4* __restrict__ w2, const float4* __restrict__ w3,
                        uint2* __restrict__ Xh, uint2* __restrict__ Wh)
{
    int i = blockIdx.x * blockDim.x + threadIdx.x;
    float4 v;
    uint2* dst;
    if (i < N4X) {
        v = x[i];
        dst = Xh + i;
    } else {
        int j = i - N4X;
        int wsel = j >> 18;            // / N4W
        int k = j & (N4W - 1);
        const float4* w = (wsel == 0) ? w0 : (wsel == 1) ? w1
                        : (wsel == 2) ? w2 : w3;
        v = w[k];
        dst = Wh + ((size_t)wsel * N4W + k);
    }
    uint2 H;
    H.x = pack_h2(v.x, v.y);
    H.y = pack_h2(v.z, v.w);
    *dst = H;
}

// =================== rope cos/sin table ====================================
__global__ void rope_table(const int* __restrict__ pos, float2* __restrict__ RT)
{
    int idx = blockIdx.x * blockDim.x + threadIdx.x;
    if (idx >= SEQ * 32) return;
    int s = idx >> 5, i = idx & 31;
    float p = (float)pos[s];
    float freq = expf(-(float)(2*i) * (9.210340371976184f / 64.f));
    float sn, cs;
    sincosf(p * freq, &sn, &cs);
    RT[idx] = make_float2(cs, sn);
}

// ===== fused QKV / WO GEMM: 128x128 CTA, 4 warps x (64x64), 3-stage ========
#define G_A 0
#define G_B 16384
#define G_STAGE 32768
#define GEMM_SMEM (3*G_STAGE)        // 96KB
#define NCHUNK (DIM/64)              // 16

// acc[m][n][4]: m = 4 m16 tiles, n = 8 n8 frags (64 cols)
__device__ __forceinline__ void gemm_core(
    const __half* __restrict__ A, const __half* __restrict__ B,
    float acc[4][8][4], uint32_t sb, int tid)
{
    const int lane = tid & 31;
    const int wm   = (tid >> 5) >> 1;        // 0..1
    const int wn   = (tid >> 5) & 1;         // 0..1
    const int rin  = lane & 7;
    const int sel  = lane >> 3;

#define G_LOAD(stg, kc) do {                                                  \
    uint32_t _s = sb + (stg) * G_STAGE;                                       \
    const int _k0 = (kc) * 64;                                                \
    _Pragma("unroll")                                                         \
    for (int _j = 0; _j < 8; _j++) {                                          \
        int _c = tid + _j * 128;                                              \
        int _r = _c >> 3, _ch = _c & 7;                                       \
        uint32_t _sw = sw128((uint32_t)(_r * 128 + _ch * 16));                \
        cp_async16(_s + G_A + _sw, A + (size_t)_r * DIM + _k0 + _ch * 8);     \
        cp_async16(_s + G_B + _sw, B + (size_t)_r * DIM + _k0 + _ch * 8);     \
    }                                                                         \
    CP_COMMIT();                                                              \
} while (0)

    G_LOAD(0, 0);
    G_LOAD(1, 1);
    G_LOAD(2, 2);

    for (int kc = 0; kc < NCHUNK; kc++) {
        if (kc + 1 >= NCHUNK)      { CP_WAIT(0); }
        else if (kc + 2 >= NCHUNK) { CP_WAIT(1); }
        else                       { CP_WAIT(2); }
        __syncthreads();
        const uint32_t stg = sb + (kc % 3) * G_STAGE;

        #pragma unroll
        for (int ks = 0; ks < 4; ks++) {
            uint32_t av[4][4];
            #pragma unroll
            for (int m = 0; m < 4; m++) {
                int row = wm*64 + m*16 + (sel & 1)*8 + rin;
                int ch  = 2*ks + (sel >> 1);
                uint32_t sw = sw128((uint32_t)(row*128 + ch*16));
                ldsm_x4(av[m][0], av[m][1], av[m][2], av[m][3], stg + G_A + sw);
            }
            uint32_t bv[8][2];
            #pragma unroll
            for (int nf = 0; nf < 4; nf++) {
                int row = wn*64 + nf*16 + (sel >> 1)*8 + rin;
                int ch  = 2*ks + (sel & 1);
                uint32_t sw = sw128((uint32_t)(row*128 + ch*16));
                uint32_t r0, r1, r2, r3;
                ldsm_x4(r0, r1, r2, r3, stg + G_B + sw);
                bv[nf*2+0][0] = r0; bv[nf*2+0][1] = r1;
                bv[nf*2+1][0] = r2; bv[nf*2+1][1] = r3;
            }
            #pragma unroll
            for (int m = 0; m < 4; m++)
                #pragma unroll
                for (int n = 0; n < 8; n++)
                    mma_fp16(acc[m][n], av[m], bv[n]);
        }
        __syncthreads();
        if (kc + 3 < NCHUNK) G_LOAD(kc % 3, kc + 3);
    }
#undef G_LOAD
}

__global__ __launch_bounds__(128, 2)
void gemm_qkv(const __half* __restrict__ Xh, const __half* __restrict__ Wh,
              const float2* __restrict__ RT,
              __half* __restrict__ Qh, __half* __restrict__ Kh,
              __half* __restrict__ Vth)
{
    extern __shared__ char smem[];
    const uint32_t sb = smem_u32(smem);
    const int tid  = threadIdx.x;
    const int lane = tid & 31;
    const int wm   = (tid >> 5) >> 1;
    const int wn   = (tid >> 5) & 1;

    const int op  = blockIdx.x >> 3;       // 0:Q 1:K 2:V
    const int bxl = blockIdx.x & 7;

    const __half* A = Xh + (size_t)(blockIdx.y * 128) * DIM;
    const __half* B = Wh + (size_t)op * DIM * DIM + (size_t)(bxl * 128) * DIM;

    float acc[4][8][4];
    #pragma unroll
    for (int m = 0; m < 4; m++)
        #pragma unroll
        for (int n = 0; n < 8; n++)
            #pragma unroll
            for (int j = 0; j < 4; j++) acc[m][n][j] = 0.f;

    gemm_core(A, B, acc, sb, tid);

    const int lrow = wm * 64 + (lane >> 2);          // local row
    const int lcol = wn * 64 + (lane & 3) * 2;       // local col (even)

    if (op < 2) {
        // ---- Q/K epilogue: rope + fp16 store ----
        __half* dst = (op == 0) ? Qh : Kh;
        const float scale = (op == 0) ? QSCALE : 1.0f;
        #pragma unroll
        for (int m = 0; m < 4; m++) {
            #pragma unroll
            for (int n = 0; n < 8; n++) {
                int col = bxl * 128 + lcol + n * 8;
                int i   = (col >> 1) & 31;
                #pragma unroll
                for (int half_ = 0; half_ < 2; half_++) {
                    int row = blockIdx.y * 128 + lrow + m * 16 + half_ * 8;
                    int s   = row & (SEQ - 1);
                    float2 cs = RT[s * 32 + i];
                    float a0 = acc[m][n][half_*2 + 0];
                    float a1 = acc[m][n][half_*2 + 1];
                    float o0 = (a0 * cs.x - a1 * cs.y) * scale;
                    float o1 = (a0 * cs.y + a1 * cs.x) * scale;
                    *(uint32_t*)(dst + (size_t)row * DIM + col) = pack_h2(o0, o1);
                }
            }
        }
    } else {
        // ---- V epilogue: transpose via smem, write Vt[(b,h,d)][s] fp16 ----
        __half (*vt)[130] = (__half(*)[130])smem;
        #pragma unroll
        for (int m = 0; m < 4; m++) {
            #pragma unroll
            for (int n = 0; n < 8; n++) {
                int r = lrow + m * 16;
                int c = lcol + n * 8;
                *(uint32_t*)&vt[r][c]   = pack_h2(acc[m][n][0], acc[m][n][1]);
                *(uint32_t*)&vt[r+8][c] = pack_h2(acc[m][n][2], acc[m][n][3]);
            }
        }
        __syncthreads();
        const int bglob = (blockIdx.y * 128) >> 11;      // batch
        const int s0    = (blockIdx.y * 128) & (SEQ-1);
        #pragma unroll
        for (int it = 0; it < 16; it++) {
            int idx = tid + it * 128;        // 0..2047
            int dl  = idx >> 4;              // local dim 0..127
            int ch  = idx & 15;              // seq chunk (8 halves)
            __half tmp[8];
            #pragma unroll
            for (int k = 0; k < 8; k++) tmp[k] = vt[ch*8 + k][dl];
            int colg = bxl * 128 + dl;
            int h = colg >> 6, d = colg & 63;
            size_t dstoff = (size_t)((bglob * NHEAD + h) * 64 + d) * SEQ + s0 + ch * 8;
            *(uint4*)(Vth + dstoff) = *(uint4*)tmp;
        }
    }
}

// ================= WO GEMM: out = Oh * Wo^T (fp32 out) =====================
__global__ __launch_bounds__(128, 2)
void gemm_wo(const __half* __restrict__ Oh, const __half* __restrict__ Wh,
             float* __restrict__ C)
{
    extern __shared__ char smem[];
    const uint32_t sb = smem_u32(smem);
    const int tid  = threadIdx.x;
    const int lane = tid & 31;
    const int wm   = (tid >> 5) >> 1;
    const int wn   = (tid >> 5) & 1;

    const __half* A = Oh + (size_t)(blockIdx.y * 128) * DIM;
    const __half* B = Wh + (size_t)3 * DIM * DIM + (size_t)(blockIdx.x * 128) * DIM;

    float acc[4][8][4];
    #pragma unroll
    for (int m = 0; m < 4; m++)
        #pragma unroll
        for (int n = 0; n < 8; n++)
            #pragma unroll
            for (int j = 0; j < 4; j++) acc[m][n][j] = 0.f;

    gemm_core(A, B, acc, sb, tid);

    const int erow = blockIdx.y * 128 + wm * 64 + (lane >> 2);
    const int ecol = blockIdx.x * 128 + wn * 64 + (lane & 3) * 2;
    #pragma unroll
    for (int m = 0; m < 4; m++) {
        #pragma unroll
        for (int n = 0; n < 8; n++) {
            float* p0 = C + (size_t)(erow + m * 16) * DIM + ecol + n * 8;
            float* p1 = p0 + (size_t)8 * DIM;
            *(float2*)p0 = make_float2(acc[m][n][0], acc[m][n][1]);
            *(float2*)p1 = make_float2(acc[m][n][2], acc[m][n][3]);
        }
    }
}

// ====== flash attention: 128-row q tile, 3-stage KV, f16x2 exp2 ============
#define F_QH  0
#define F_STG 16384
#define F_K   0
#define F_V   8192
#define F_STAGE_BYTES 16384
#define FLASH_SMEM (16384 + 3*F_STAGE_BYTES)   // 64KB

__global__ __launch_bounds__(128, 2)
void flash_f16(const __half* __restrict__ Qh, const __half* __restrict__ Kh,
               const __half* __restrict__ Vth, __half* __restrict__ Oh)
{
    extern __shared__ char smem[];
    const uint32_t sb = smem_u32(smem);
    const int tid  = threadIdx.x;
    const int lane = tid & 31;
    const int w    = tid >> 5;
    const int g    = lane >> 2;
    const int t    = lane & 3;
    const int rin  = lane & 7;
    const int sel  = lane >> 3;

    const int bq = (SEQ/128 - 1) - blockIdx.x;   // heavy tiles first
    const int h  = blockIdx.y;
    const int b  = blockIdx.z;

    const int nblk = 2*bq + 2;

    // ---- prologue: Q tile (128 rows) + KV stages 0,1 ----
    {
        const size_t qbase = (size_t)(b*SEQ + bq*128);
        #pragma unroll
        for (int j = 0; j < 8; j++) {
            int c = tid + j*128;             // 0..1023
            int r = c >> 3, ch = c & 7;
            uint32_t sw = sw128((uint32_t)(r*128 + ch*16));
            cp_async16(sb + F_QH + sw, Qh + (qbase + r)*DIM + h*64 + ch*8);
        }
    }

#define LOAD_KV(stg, blk) do {                                                 \
    uint32_t _s = sb + F_STG + (stg)*F_STAGE_BYTES;                            \
    const int _k0 = (blk)*64;                                                  \
    _Pragma("unroll")                                                          \
    for (int _j = 0; _j < 4; _j++) {                                           \
        int _c = tid + _j*128;                                                 \
        int _r = _c >> 3, _ch = _c & 7;                                        \
        uint32_t _sw = sw128((uint32_t)(_r*128 + _ch*16));                     \
        cp_async16(_s + F_K + _sw,                                             \
                   Kh + (size_t)(b*SEQ + _k0 + _r)*DIM + h*64 + _ch*8);        \
        cp_async16(_s + F_V + _sw,                                             \
                   Vth + (size_t)((b*NHEAD + h)*64 + _r)*SEQ + _k0 + _ch*8);   \
    }                                                                          \
} while (0)

    LOAD_KV(0, 0);
    CP_COMMIT();            // group0: Q + KV0
    LOAD_KV(1, 1);
    CP_COMMIT();            // group1: KV1

    CP_WAIT(1);             // Q + KV0 ready
    __syncthreads();

    // ---- Q fragments: 2 m16 tiles x 4 k-chunks ----
    uint32_t qv[2][4][4];
    #pragma unroll
    for (int mt = 0; mt < 2; mt++) {
        #pragma unroll
        for (int kk = 0; kk < 4; kk++) {
            int row = w*32 + mt*16 + (sel & 1)*8 + rin;
            int ch  = 2*kk + (sel >> 1);
            uint32_t sw = sw128((uint32_t)(row*128 + ch*16));
            ldsm_x4(qv[mt][kk][0], qv[mt][kk][1], qv[mt][kk][2], qv[mt][kk][3],
                    sb + F_QH + sw);
        }
    }

    float O[2][8][4];
    #pragma unroll
    for (int mt = 0; mt < 2; mt++)
        #pragma unroll
        for (int f = 0; f < 8; f++)
            #pragma unroll
            for (int j = 0; j < 4; j++) O[mt][f][j] = 0.f;
    float L[2][4] = {{0.f,0.f,0.f,0.f},{0.f,0.f,0.f,0.f}};
    const uint32_t ones2 = 0x3C003C00u;
    const uint32_t ones_b[2] = {ones2, ones2};

    for (int i = 0; i < nblk; i++) {
        if (i > 0) {
            if (i == nblk - 1) { CP_WAIT(0); } else { CP_WAIT(1); }
            __syncthreads();
        }
        if (i + 2 < nblk) {
            LOAD_KV((i + 2) % 3, i + 2);
            CP_COMMIT();
        }
        const uint32_t kb = sb + F_STG + (i % 3)*F_STAGE_BYTES;

        // ---- S = Q * K^T for both m-tiles (K frags loaded once) ----
        float S[2][8][4];
        #pragma unroll
        for (int mt = 0; mt < 2; mt++)
            #pragma unroll
            for (int f = 0; f < 8; f++)
                #pragma unroll
                for (int j = 0; j < 4; j++) S[mt][f][j] = 0.f;

        #pragma unroll
        for (int kk = 0; kk < 4; kk++) {
            #pragma unroll
            for (int nfp = 0; nfp < 4; nfp++) {
                int row = nfp*16 + (sel >> 1)*8 + rin;
                int ch  = 2*kk + (sel & 1);
                uint32_t sw = sw128((uint32_t)(row*128 + ch*16));
                uint32_t k0r, k1r, k2r, k3r;
                ldsm_x4(k0r, k1r, k2r, k3r, kb + F_K + sw);
                uint32_t b0[2] = {k0r, k1r}, b1[2] = {k2r, k3r};
                #pragma unroll
                for (int mt = 0; mt < 2; mt++) {
                    mma_fp16(S[mt][nfp*2],   qv[mt][kk], b0);
                    mma_fp16(S[mt][nfp*2+1], qv[mt][kk], b1);
                }
            }
        }

        // ---- causal mask (last two key blocks cross the diagonal) ----
        if (i >= nblk - 2) {
            #pragma unroll
            for (int mt = 0; mt < 2; mt++) {
                int r0 = w*32 + mt*16 + g;       // q row rel. to tile start
                int r1 = r0 + 8;
                #pragma unroll
                for (int f = 0; f < 8; f++) {
                    int kl = i*64 + f*8 + 2*t - bq*128;  // key rel. to tile start
                    if (kl     > r0) S[mt][f][0] = -1e30f;
                    if (kl + 1 > r0) S[mt][f][1] = -1e30f;
                    if (kl     > r1) S[mt][f][2] = -1e30f;
                    if (kl + 1 > r1) S[mt][f][3] = -1e30f;
                }
            }
        }

        // ---- O += exp2(S)*V ; L += exp2(S)*ones  (exp2 fused into pack) ----
        #pragma unroll
        for (int kk = 0; kk < 4; kk++) {
            uint32_t ap[2][4];
            #pragma unroll
            for (int mt = 0; mt < 2; mt++) {
                ap[mt][0] = ex2_h2(S[mt][2*kk][0],   S[mt][2*kk][1]);
                ap[mt][1] = ex2_h2(S[mt][2*kk][2],   S[mt][2*kk][3]);
                ap[mt][2] = ex2_h2(S[mt][2*kk+1][0], S[mt][2*kk+1][1]);
                ap[mt][3] = ex2_h2(S[mt][2*kk+1][2], S[mt][2*kk+1][3]);
                mma_fp16(L[mt], ap[mt], ones_b);
            }
            #pragma unroll
            for (int nfp = 0; nfp < 4; nfp++) {
                int row = nfp*16 + (sel >> 1)*8 + rin;
                int ch  = 2*kk + (sel & 1);
                uint32_t sw = sw128((uint32_t)(row*128 + ch*16));
                uint32_t v0, v1, v2, v3;
                ldsm_x4(v0, v1, v2, v3, kb + F_V + sw);
                uint32_t b0[2] = {v0, v1}, b1[2] = {v2, v3};
                #pragma unroll
                for (int mt = 0; mt < 2; mt++) {
                    mma_fp16(O[mt][nfp*2],   ap[mt], b0);
                    mma_fp16(O[mt][nfp*2+1], ap[mt], b1);
                }
            }
        }
    }

    // ---- epilogue: normalize + fp16 store ----
    #pragma unroll
    for (int mt = 0; mt < 2; mt++) {
        const float inv0 = 1.0f / L[mt][0];
        const float inv1 = 1.0f / L[mt][2];
        const size_t row0 = (size_t)(b*SEQ + bq*128 + w*32 + mt*16 + g);
        const size_t row1 = row0 + 8;
        #pragma unroll
        for (int f = 0; f < 8; f++) {
            int col = h*64 + f*8 + 2*t;
            *(uint32_t*)(Oh + row0*DIM + col) = pack_h2(O[mt][f][0]*inv0, O[mt][f][1]*inv0);
            *(uint32_t*)(Oh + row1*DIM + col) = pack_h2(O[mt][f][2]*inv1, O[mt][f][3]*inv1);
        }
    }
}

// ---------------- launch ---------------------------------------------------
extern "C" void kernel_launch(void* const* d_in, const int* in_sizes, int n_in,
                              void* d_out, int out_size)
{
    const float* x   = (const float*)d_in[0];
    const int*   pos = (const int*)  d_in[1];
    const float* wq  = (const float*)d_in[2];
    const float* wk  = (const float*)d_in[3];
    const float* wv  = (const float*)d_in[4];
    const float* wo  = (const float*)d_in[5];
    float* out = (float*)d_out;

    __half *Xh, *Wh, *Qh, *Kh, *Vth, *Oh;
    float2* RT;
    cudaGetSymbolAddress((void**)&Xh, g_Xh);
    cudaGetSymbolAddress((void**)&Wh, g_Wh);
    cudaGetSymbolAddress((void**)&Qh, g_Qh);
    cudaGetSymbolAddress((void**)&Kh, g_Kh);
    cudaGetSymbolAddress((void**)&Vth, g_Vth);
    cudaGetSymbolAddress((void**)&Oh, g_Oh);
    cudaGetSymbolAddress((void**)&RT, g_RT);

    cudaFuncSetAttribute(gemm_qkv,
                         cudaFuncAttributeMaxDynamicSharedMemorySize, GEMM_SMEM);
    cudaFuncSetAttribute(gemm_wo,
                         cudaFuncAttributeMaxDynamicSharedMemorySize, GEMM_SMEM);
    cudaFuncSetAttribute(flash_f16,
                         cudaFuncAttributeMaxDynamicSharedMemorySize, FLASH_SMEM);

    const int ntot = N4X + 4 * N4W;
    cvt_all<<<(ntot + 255)/256, 256>>>((const float4*)x,
        (const float4*)wq, (const float4*)wk, (const float4*)wv, (const float4*)wo,
        (uint2*)Xh, (uint2*)Wh);

    rope_table<<<(SEQ*32 + 255)/256, 256>>>(pos, RT);

    gemm_qkv<<<dim3(24, MROWS/128), 128, GEMM_SMEM>>>(Xh, Wh, RT, Qh, Kh, Vth);

    flash_f16<<<dim3(SEQ/128, NHEAD, BATCH), 128, FLASH_SMEM>>>(Qh, Kh, Vth, Oh);

    gemm_wo<<<dim3(DIM/128, MROWS/128), 128, GEMM_SMEM>>>(Oh, Wh, out);
}